// round 5
// baseline (speedup 1.0000x reference)
#include <cuda_runtime.h>
#include <cuda_fp16.h>
#include <cstdint>
#include <cstddef>

#define DIM   768
#define NOUT  2304
#define RANK  16
#define MTOT  32768
#define BM    128
#define BN    256
#define BK    64
#define KT    12          // 768/64
#define NSTG  3
#define STG_A 16384       // 128 rows * 128B
#define STGB  49152       // A(16K) + B(32K)
#define SMEM_TOTAL (1024 + NSTG * STGB)   // 148480

__device__ __align__(1024) __half g_wh[NOUT * DIM];
__device__ __align__(1024) __half g_xh[MTOT * DIM];

__device__ __forceinline__ uint32_t smem_u32(const void* p) {
    uint32_t a;
    asm("{ .reg .u64 t; cvta.to.shared.u64 t, %1; cvt.u32.u64 %0, t; }" : "=r"(a) : "l"(p));
    return a;
}
#define CP16(dst, src) \
    asm volatile("cp.async.cg.shared.global [%0], [%1], 16;" :: "r"(dst), "l"(src))
#define CP_COMMIT() asm volatile("cp.async.commit_group;" ::: "memory")
#define CP_WAIT1()  asm volatile("cp.async.wait_group 1;" ::: "memory")
#define LDSM_X4(r0, r1, r2, r3, addr) \
    asm volatile("ldmatrix.sync.aligned.m8n8.x4.shared.b16 {%0,%1,%2,%3}, [%4];" \
        : "=r"(r0), "=r"(r1), "=r"(r2), "=r"(r3) : "r"(addr))
#define MMA16816(c, a, b0v, b1v) \
    asm volatile("mma.sync.aligned.m16n8k16.row.col.f32.f16.f16.f32 " \
        "{%0,%1,%2,%3}, {%4,%5,%6,%7}, {%8,%9}, {%0,%1,%2,%3};" \
        : "+f"((c)[0]), "+f"((c)[1]), "+f"((c)[2]), "+f"((c)[3]) \
        : "r"((a)[0]), "r"((a)[1]), "r"((a)[2]), "r"((a)[3]), "r"(b0v), "r"(b1v))

// Merged prep: blocks [0, nConvBlk) convert x -> fp16; rest fold LoRA into fp16 Weff.
__global__ void prep_kernel(const float* __restrict__ x, int n8, int nConvBlk,
                            const float* __restrict__ W,
                            const float* __restrict__ Aq, const float* __restrict__ Bq,
                            const float* __restrict__ Ak, const float* __restrict__ Bk,
                            const float* __restrict__ Av, const float* __restrict__ Bv) {
    if (blockIdx.x < (unsigned)nConvBlk) {
        int i = blockIdx.x * 256 + threadIdx.x;
        if (i >= n8) return;
        float4 v0 = reinterpret_cast<const float4*>(x)[i * 2];
        float4 v1 = reinterpret_cast<const float4*>(x)[i * 2 + 1];
        __half2 h[4];
        h[0] = __float22half2_rn(make_float2(v0.x, v0.y));
        h[1] = __float22half2_rn(make_float2(v0.z, v0.w));
        h[2] = __float22half2_rn(make_float2(v1.x, v1.y));
        h[3] = __float22half2_rn(make_float2(v1.z, v1.w));
        reinterpret_cast<uint4*>(g_xh)[i] = *reinterpret_cast<uint4*>(h);
    } else {
        int idx = (blockIdx.x - nConvBlk) * 256 + threadIdx.x;
        if (idx >= NOUT * DIM) return;
        int o = idx / DIM;
        int d = idx - o * DIM;
        int s = o / DIM;
        int op = o - s * DIM;
        const float* A = (s == 0) ? Aq : (s == 1) ? Ak : Av;
        const float* B = (s == 0) ? Bq : (s == 1) ? Bk : Bv;
        float acc = W[idx];
#pragma unroll
        for (int r = 0; r < RANK; r++) acc += B[op * RANK + r] * A[r * DIM + d];
        g_wh[idx] = __float2half_rn(acc);
    }
}

// out[m][n] = sum_k xh[m][k] * wh[n][k] + bias[n]
// Block 128x256, BK=64, 8 warps in 2(M) x 4(N), warp tile 64x64.
__global__ __launch_bounds__(256, 1) void gemm_f16(const float* __restrict__ bias,
                                                   float* __restrict__ out) {
    extern __shared__ __align__(1024) char smem[];
    float* bsm = reinterpret_cast<float*>(smem);
    const uint32_t sbase = smem_u32(smem + 1024);

    const int tid = threadIdx.x;
    const int lane = tid & 31;
    const int wid = tid >> 5;
    const int wm = wid >> 2;         // 0..1 -> rows wm*64
    const int wn = wid & 3;          // 0..3 -> cols wn*64
    const int gm0 = blockIdx.y * BM;
    const int gn0 = blockIdx.x * BN;

    bsm[tid] = bias[gn0 + tid];

    const __half* gA = g_xh + (size_t)gm0 * DIM;
    const __half* gB = g_wh + (size_t)gn0 * DIM;

    const int ldr = tid >> 3;            // 0..31
    const int ldc = tid & 7;             // 16B chunk in 128B row

    float acc[4][8][4];
#pragma unroll
    for (int i = 0; i < 4; i++)
#pragma unroll
        for (int n = 0; n < 8; n++)
#pragma unroll
            for (int t = 0; t < 4; t++) acc[i][n][t] = 0.0f;

#pragma unroll
    for (int p = 0; p < NSTG - 1; p++) {
        uint32_t st = sbase + p * STGB;
        const __half* a = gA + p * BK;
        const __half* b = gB + p * BK;
#pragma unroll
        for (int i = 0; i < 4; i++) {
            int r = ldr + i * 32;
            uint32_t off = (uint32_t)(r * 128) + (uint32_t)(((ldc ^ (r & 7)) << 4));
            CP16(st + off, a + (size_t)r * DIM + ldc * 8);
        }
#pragma unroll
        for (int i = 0; i < 8; i++) {
            int r = ldr + i * 32;
            uint32_t off = (uint32_t)(r * 128) + (uint32_t)(((ldc ^ (r & 7)) << 4));
            CP16(st + STG_A + off, b + (size_t)r * DIM + ldc * 8);
        }
        CP_COMMIT();
    }

    for (int kt = 0; kt < KT; kt++) {
        CP_WAIT1();
        __syncthreads();

        int nk = kt + NSTG - 1;
        if (nk < KT) {
            uint32_t st = sbase + (nk % NSTG) * STGB;
            const __half* a = gA + nk * BK;
            const __half* b = gB + nk * BK;
#pragma unroll
            for (int i = 0; i < 4; i++) {
                int r = ldr + i * 32;
                uint32_t off = (uint32_t)(r * 128) + (uint32_t)(((ldc ^ (r & 7)) << 4));
                CP16(st + off, a + (size_t)r * DIM + ldc * 8);
            }
#pragma unroll
            for (int i = 0; i < 8; i++) {
                int r = ldr + i * 32;
                uint32_t off = (uint32_t)(r * 128) + (uint32_t)(((ldc ^ (r & 7)) << 4));
                CP16(st + STG_A + off, b + (size_t)r * DIM + ldc * 8);
            }
        }
        CP_COMMIT();

        const uint32_t stA = sbase + (kt % NSTG) * STGB;
        const uint32_t stB = stA + STG_A;
        const int rowA = wm * 64 + (lane & 15);
        const int rowB = wn * 64 + (lane & 15);

#pragma unroll
        for (int kk = 0; kk < 4; kk++) {
            const int cb = kk * 2 + (lane >> 4);
            uint32_t af[4][4];
            uint32_t aaddr = stA + (uint32_t)(rowA * 128) + (uint32_t)(((cb ^ (rowA & 7)) << 4));
#pragma unroll
            for (int i = 0; i < 4; i++)
                LDSM_X4(af[i][0], af[i][1], af[i][2], af[i][3], aaddr + i * 16 * 128);

            uint32_t bf[4][4];
            uint32_t baddr = stB + (uint32_t)(rowB * 128) + (uint32_t)(((cb ^ (rowB & 7)) << 4));
#pragma unroll
            for (int j = 0; j < 4; j++)
                LDSM_X4(bf[j][0], bf[j][1], bf[j][2], bf[j][3], baddr + j * 16 * 128);

#pragma unroll
            for (int i = 0; i < 4; i++)
#pragma unroll
                for (int n = 0; n < 8; n++) {
                    int j = n >> 1, h = n & 1;
                    MMA16816(acc[i][n], af[i], bf[j][h], bf[j][h + 2]);
                }
        }
    }

    // Epilogue: float2 stores, bias from smem
    const int r0 = wm * 64 + (lane >> 2);
    const int c0 = wn * 64 + (lane & 3) * 2;
    float* ob = out + (size_t)gm0 * NOUT + gn0;
#pragma unroll
    for (int i = 0; i < 4; i++) {
        int row = r0 + i * 16;
#pragma unroll
        for (int n = 0; n < 8; n++) {
            int col = c0 + n * 8;
            float b0 = bsm[col], b1 = bsm[col + 1];
            float2 v0 = make_float2(acc[i][n][0] + b0, acc[i][n][1] + b1);
            float2 v1 = make_float2(acc[i][n][2] + b0, acc[i][n][3] + b1);
            *reinterpret_cast<float2*>(ob + (size_t)row * NOUT + col) = v0;
            *reinterpret_cast<float2*>(ob + (size_t)(row + 8) * NOUT + col) = v1;
        }
    }
}

extern "C" void kernel_launch(void* const* d_in, const int* in_sizes, int n_in,
                              void* d_out, int out_size) {
    const float* x    = (const float*)d_in[0];
    const float* Wqkv = (const float*)d_in[1];
    const float* bqkv = (const float*)d_in[2];
    const float* Aq   = (const float*)d_in[3];
    const float* Bq   = (const float*)d_in[4];
    const float* Ak   = (const float*)d_in[5];
    const float* Bk   = (const float*)d_in[6];
    const float* Av   = (const float*)d_in[7];
    const float* Bv   = (const float*)d_in[8];
    float* out = (float*)d_out;

    int M = in_sizes[0] / DIM;   // 32768
    cudaFuncSetAttribute(gemm_f16, cudaFuncAttributeMaxDynamicSharedMemorySize, SMEM_TOTAL);

    int n8 = M * DIM / 8;
    int nConvBlk = (n8 + 255) / 256;
    int nFoldBlk = (NOUT * DIM + 255) / 256;
    prep_kernel<<<nConvBlk + nFoldBlk, 256>>>(x, n8, nConvBlk, Wqkv, Aq, Bq, Ak, Bk, Av, Bv);

    dim3 grid(NOUT / BN, M / BM);   // 9 x 256
    gemm_f16<<<grid, 256, SMEM_TOTAL>>>(bqkv, out);
}

// round 6
// speedup vs baseline: 1.1166x; 1.1166x over previous
#include <cuda_runtime.h>
#include <cuda_fp16.h>
#include <cstdint>
#include <cstddef>

#define DIM   768
#define NOUT  2304
#define RANK  16
#define MTOT  32768
#define BM    128
#define BN    128
#define BK    64
#define KT    12          // 768/64
#define NSTG  3
#define STG_A 16384       // 128 rows * 128B
#define STGB  32768
#define SMEM_TOTAL (512 + NSTG * STGB)   // 98816 -> 2 CTAs/SM

__device__ __align__(1024) __half g_wh[NOUT * DIM];
__device__ __align__(1024) __half g_xh[MTOT * DIM];

__device__ __forceinline__ uint32_t smem_u32(const void* p) {
    uint32_t a;
    asm("{ .reg .u64 t; cvta.to.shared.u64 t, %1; cvt.u32.u64 %0, t; }" : "=r"(a) : "l"(p));
    return a;
}
#define CP16(dst, src) \
    asm volatile("cp.async.cg.shared.global [%0], [%1], 16;" :: "r"(dst), "l"(src))
#define CP_COMMIT() asm volatile("cp.async.commit_group;" ::: "memory")
#define CP_WAIT1()  asm volatile("cp.async.wait_group 1;" ::: "memory")
#define LDSM_X4(r0, r1, r2, r3, addr) \
    asm volatile("ldmatrix.sync.aligned.m8n8.x4.shared.b16 {%0,%1,%2,%3}, [%4];" \
        : "=r"(r0), "=r"(r1), "=r"(r2), "=r"(r3) : "r"(addr))
#define MMA16816(c, a, b0v, b1v) \
    asm volatile("mma.sync.aligned.m16n8k16.row.col.f32.f16.f16.f32 " \
        "{%0,%1,%2,%3}, {%4,%5,%6,%7}, {%8,%9}, {%0,%1,%2,%3};" \
        : "+f"((c)[0]), "+f"((c)[1]), "+f"((c)[2]), "+f"((c)[3]) \
        : "r"((a)[0]), "r"((a)[1]), "r"((a)[2]), "r"((a)[3]), "r"(b0v), "r"(b1v))

// Merged prep: blocks [0, nConvBlk) convert x -> fp16; rest fold LoRA into fp16 Weff.
__global__ void prep_kernel(const float* __restrict__ x, int n8, int nConvBlk,
                            const float* __restrict__ W,
                            const float* __restrict__ Aq, const float* __restrict__ Bq,
                            const float* __restrict__ Ak, const float* __restrict__ Bk,
                            const float* __restrict__ Av, const float* __restrict__ Bv) {
    if (blockIdx.x < (unsigned)nConvBlk) {
        int i = blockIdx.x * 256 + threadIdx.x;
        if (i >= n8) return;
        float4 v0 = reinterpret_cast<const float4*>(x)[i * 2];
        float4 v1 = reinterpret_cast<const float4*>(x)[i * 2 + 1];
        __half2 h[4];
        h[0] = __float22half2_rn(make_float2(v0.x, v0.y));
        h[1] = __float22half2_rn(make_float2(v0.z, v0.w));
        h[2] = __float22half2_rn(make_float2(v1.x, v1.y));
        h[3] = __float22half2_rn(make_float2(v1.z, v1.w));
        reinterpret_cast<uint4*>(g_xh)[i] = *reinterpret_cast<uint4*>(h);
    } else {
        int idx = (blockIdx.x - nConvBlk) * 256 + threadIdx.x;
        if (idx >= NOUT * DIM) return;
        int o = idx / DIM;
        int d = idx - o * DIM;
        int s = o / DIM;
        int op = o - s * DIM;
        const float* A = (s == 0) ? Aq : (s == 1) ? Ak : Av;
        const float* B = (s == 0) ? Bq : (s == 1) ? Bk : Bv;
        float acc = W[idx];
#pragma unroll
        for (int r = 0; r < RANK; r++) acc += B[op * RANK + r] * A[r * DIM + d];
        g_wh[idx] = __float2half_rn(acc);
    }
}

// out[m][n] = sum_k xh[m][k] * wh[n][k] + bias[n]
// Block 128x128, 8 warps in 4(M) x 2(N), warp tile 32x64, 2 CTAs/SM.
__global__ __launch_bounds__(256, 2) void gemm_f16(const float* __restrict__ bias,
                                                   float* __restrict__ out) {
    extern __shared__ __align__(1024) char smem[];
    float* bsm = reinterpret_cast<float*>(smem);
    const uint32_t sbase = smem_u32(smem + 512);

    const int tid = threadIdx.x;
    const int lane = tid & 31;
    const int wid = tid >> 5;
    const int wm = wid & 3;          // rows wm*32
    const int wn = wid >> 2;         // cols wn*64
    const int gm0 = blockIdx.y * BM;
    const int gn0 = blockIdx.x * BN;

    if (tid < 128) bsm[tid] = bias[gn0 + tid];

    // ---- hoisted cp.async addressing ----
    const int ldr = tid >> 3;            // 0..31
    const int ldc = tid & 7;
    uint32_t soff[4];                    // swizzled smem offsets for rows ldr+32i
#pragma unroll
    for (int i = 0; i < 4; i++) {
        int r = ldr + i * 32;
        soff[i] = (uint32_t)(r * 128) + (uint32_t)(((ldc ^ (r & 7)) << 4));
    }
    const __half* aSrc = g_xh + (size_t)gm0 * DIM + (size_t)ldr * DIM + ldc * 8;
    const __half* bSrc = g_wh + (size_t)gn0 * DIM + (size_t)ldr * DIM + ldc * 8;
    const size_t rstep = (size_t)32 * DIM;

    // ---- hoisted ldmatrix base offsets ----
    const int rowA = wm * 32 + (lane & 15);
    const int rowB = wn * 64 + (lane & 15);
    const uint32_t aSwz = (uint32_t)(rowA * 128);
    const uint32_t bSwz = (uint32_t)(rowB * 128);
    const int swzA = rowA & 7, swzB = rowB & 7;

    float acc[2][8][4];
#pragma unroll
    for (int i = 0; i < 2; i++)
#pragma unroll
        for (int n = 0; n < 8; n++)
#pragma unroll
            for (int t = 0; t < 4; t++) acc[i][n][t] = 0.0f;

#pragma unroll
    for (int p = 0; p < NSTG - 1; p++) {
        uint32_t st = sbase + p * STGB;
#pragma unroll
        for (int i = 0; i < 4; i++) {
            CP16(st + soff[i], aSrc + p * BK + i * rstep);
            CP16(st + STG_A + soff[i], bSrc + p * BK + i * rstep);
        }
        CP_COMMIT();
    }

    for (int kt = 0; kt < KT; kt++) {
        CP_WAIT1();
        __syncthreads();

        int nk = kt + NSTG - 1;
        if (nk < KT) {
            uint32_t st = sbase + (nk % NSTG) * STGB;
#pragma unroll
            for (int i = 0; i < 4; i++) {
                CP16(st + soff[i], aSrc + nk * BK + i * rstep);
                CP16(st + STG_A + soff[i], bSrc + nk * BK + i * rstep);
            }
        }
        CP_COMMIT();

        const uint32_t stA = sbase + (kt % NSTG) * STGB;
        const uint32_t stB = stA + STG_A;

#pragma unroll
        for (int kk = 0; kk < 4; kk++) {
            const int cb = kk * 2 + (lane >> 4);
            uint32_t af[2][4];
            uint32_t aaddr = stA + aSwz + (uint32_t)(((cb ^ swzA) << 4));
            LDSM_X4(af[0][0], af[0][1], af[0][2], af[0][3], aaddr);
            LDSM_X4(af[1][0], af[1][1], af[1][2], af[1][3], aaddr + 16 * 128);

            uint32_t bf[4][4];
            uint32_t baddr = stB + bSwz + (uint32_t)(((cb ^ swzB) << 4));
#pragma unroll
            for (int j = 0; j < 4; j++)
                LDSM_X4(bf[j][0], bf[j][1], bf[j][2], bf[j][3], baddr + j * 16 * 128);

#pragma unroll
            for (int i = 0; i < 2; i++)
#pragma unroll
                for (int n = 0; n < 8; n++) {
                    int j = n >> 1, h = n & 1;
                    MMA16816(acc[i][n], af[i], bf[j][h], bf[j][h + 2]);
                }
        }
    }

    // Epilogue: float2 stores, bias from smem
    const int r0 = wm * 32 + (lane >> 2);
    const int c0 = wn * 64 + (lane & 3) * 2;
    float* ob = out + (size_t)gm0 * NOUT + gn0;
#pragma unroll
    for (int i = 0; i < 2; i++) {
        int row = r0 + i * 16;
#pragma unroll
        for (int n = 0; n < 8; n++) {
            int col = c0 + n * 8;
            float b0 = bsm[col], b1 = bsm[col + 1];
            float2 v0 = make_float2(acc[i][n][0] + b0, acc[i][n][1] + b1);
            float2 v1 = make_float2(acc[i][n][2] + b0, acc[i][n][3] + b1);
            *reinterpret_cast<float2*>(ob + (size_t)row * NOUT + col) = v0;
            *reinterpret_cast<float2*>(ob + (size_t)(row + 8) * NOUT + col) = v1;
        }
    }
}

extern "C" void kernel_launch(void* const* d_in, const int* in_sizes, int n_in,
                              void* d_out, int out_size) {
    const float* x    = (const float*)d_in[0];
    const float* Wqkv = (const float*)d_in[1];
    const float* bqkv = (const float*)d_in[2];
    const float* Aq   = (const float*)d_in[3];
    const float* Bq   = (const float*)d_in[4];
    const float* Ak   = (const float*)d_in[5];
    const float* Bk   = (const float*)d_in[6];
    const float* Av   = (const float*)d_in[7];
    const float* Bv   = (const float*)d_in[8];
    float* out = (float*)d_out;

    int M = in_sizes[0] / DIM;   // 32768
    cudaFuncSetAttribute(gemm_f16, cudaFuncAttributeMaxDynamicSharedMemorySize, SMEM_TOTAL);

    int n8 = M * DIM / 8;
    int nConvBlk = (n8 + 255) / 256;
    int nFoldBlk = (NOUT * DIM + 255) / 256;
    prep_kernel<<<nConvBlk + nFoldBlk, 256>>>(x, n8, nConvBlk, Wqkv, Aq, Bq, Ak, Bk, Av, Bv);

    dim3 grid(NOUT / BN, M / BM);   // 18 x 256
    gemm_f16<<<grid, 256, SMEM_TOTAL>>>(bqkv, out);
}

// round 7
// speedup vs baseline: 1.1202x; 1.0032x over previous
#include <cuda_runtime.h>
#include <cuda_fp16.h>
#include <cstdint>
#include <cstddef>

#define DIM   768
#define NOUT  2304
#define RANK  16
#define MTOT  32768
#define BM    128
#define BN    128
#define BK    64
#define KT    12          // 768/64
#define NSTG  3
#define STG_A 16384       // 128 rows * 128B
#define STGB  32768
#define SMEM_TOTAL (512 + NSTG * STGB)   // 98816 -> 2 CTAs/SM

__device__ __align__(1024) __half g_wh[NOUT * DIM];
__device__ __align__(1024) __half g_xh[MTOT * DIM];

__device__ __forceinline__ uint32_t smem_u32(const void* p) {
    uint32_t a;
    asm("{ .reg .u64 t; cvta.to.shared.u64 t, %1; cvt.u32.u64 %0, t; }" : "=r"(a) : "l"(p));
    return a;
}
#define CP16(dst, src) \
    asm volatile("cp.async.cg.shared.global [%0], [%1], 16;" :: "r"(dst), "l"(src))
#define CP_COMMIT() asm volatile("cp.async.commit_group;" ::: "memory")
#define CP_WAIT1()  asm volatile("cp.async.wait_group 1;" ::: "memory")
#define LDSM_X4(r0, r1, r2, r3, addr) \
    asm volatile("ldmatrix.sync.aligned.m8n8.x4.shared.b16 {%0,%1,%2,%3}, [%4];" \
        : "=r"(r0), "=r"(r1), "=r"(r2), "=r"(r3) : "r"(addr))
#define MMA16816(c, a0, a1, a2, a3, b0v, b1v) \
    asm volatile("mma.sync.aligned.m16n8k16.row.col.f32.f16.f16.f32 " \
        "{%0,%1,%2,%3}, {%4,%5,%6,%7}, {%8,%9}, {%0,%1,%2,%3};" \
        : "+f"((c)[0]), "+f"((c)[1]), "+f"((c)[2]), "+f"((c)[3]) \
        : "r"(a0), "r"(a1), "r"(a2), "r"(a3), "r"(b0v), "r"(b1v))

// Merged prep: blocks [0, nConvBlk) convert x -> fp16; rest fold LoRA into fp16 Weff.
__global__ void prep_kernel(const float* __restrict__ x, int n8, int nConvBlk,
                            const float* __restrict__ W,
                            const float* __restrict__ Aq, const float* __restrict__ Bq,
                            const float* __restrict__ Ak, const float* __restrict__ Bk,
                            const float* __restrict__ Av, const float* __restrict__ Bv) {
    if (blockIdx.x < (unsigned)nConvBlk) {
        int i = blockIdx.x * 256 + threadIdx.x;
        if (i >= n8) return;
        float4 v0 = reinterpret_cast<const float4*>(x)[i * 2];
        float4 v1 = reinterpret_cast<const float4*>(x)[i * 2 + 1];
        __half2 h[4];
        h[0] = __float22half2_rn(make_float2(v0.x, v0.y));
        h[1] = __float22half2_rn(make_float2(v0.z, v0.w));
        h[2] = __float22half2_rn(make_float2(v1.x, v1.y));
        h[3] = __float22half2_rn(make_float2(v1.z, v1.w));
        reinterpret_cast<uint4*>(g_xh)[i] = *reinterpret_cast<uint4*>(h);
    } else {
        int idx = (blockIdx.x - nConvBlk) * 256 + threadIdx.x;
        if (idx >= NOUT * DIM) return;
        int o = idx / DIM;
        int d = idx - o * DIM;
        int s = o / DIM;
        int op = o - s * DIM;
        const float* A = (s == 0) ? Aq : (s == 1) ? Ak : Av;
        const float* B = (s == 0) ? Bq : (s == 1) ? Bk : Bv;
        float acc = W[idx];
#pragma unroll
        for (int r = 0; r < RANK; r++) acc += B[op * RANK + r] * A[r * DIM + d];
        g_wh[idx] = __float2half_rn(acc);
    }
}

// out[m][n] = sum_k xh[m][k] * wh[n][k] + bias[n]
// Block 128x128, 8 warps in 4(M) x 2(N), warp tile 32x64, 2 CTAs/SM.
// Register-level ping-pong: LDSM for next (kk,j) overlaps MMAs of current.
__global__ __launch_bounds__(256, 2) void gemm_f16(const float* __restrict__ bias,
                                                   float* __restrict__ out) {
    extern __shared__ __align__(1024) char smem[];
    float* bsm = reinterpret_cast<float*>(smem);
    const uint32_t sbase = smem_u32(smem + 512);

    const int tid = threadIdx.x;
    const int lane = tid & 31;
    const int wid = tid >> 5;
    const int wm = wid & 3;          // rows wm*32
    const int wn = wid >> 2;         // cols wn*64
    const int gm0 = blockIdx.y * BM;
    const int gn0 = blockIdx.x * BN;

    if (tid < 128) bsm[tid] = bias[gn0 + tid];

    // ---- hoisted cp.async addressing ----
    const int ldr = tid >> 3;            // 0..31
    const int ldc = tid & 7;
    uint32_t soff[4];
#pragma unroll
    for (int i = 0; i < 4; i++) {
        int r = ldr + i * 32;
        soff[i] = (uint32_t)(r * 128) + (uint32_t)(((ldc ^ (r & 7)) << 4));
    }
    const __half* aSrc = g_xh + (size_t)gm0 * DIM + (size_t)ldr * DIM + ldc * 8;
    const __half* bSrc = g_wh + (size_t)gn0 * DIM + (size_t)ldr * DIM + ldc * 8;
    const size_t rstep = (size_t)32 * DIM;

    // ---- hoisted ldmatrix swizzle offsets: off(cb) = ((cb^swz)<<4), cb = kk*2+(lane>>4)
    const int rowA = wm * 32 + (lane & 15);
    const int rowB = wn * 64 + (lane & 15);
    const int cbh = lane >> 4;
    const uint32_t aBase = (uint32_t)(rowA * 128);
    const uint32_t bBase = (uint32_t)(rowB * 128);
    uint32_t aoff[4], boff[4];           // per-kk swizzled column offsets
#pragma unroll
    for (int kk = 0; kk < 4; kk++) {
        int cb = kk * 2 + cbh;
        aoff[kk] = aBase + (uint32_t)(((cb ^ (rowA & 7)) << 4));
        boff[kk] = bBase + (uint32_t)(((cb ^ (rowB & 7)) << 4));
    }

    float acc[2][8][4];
#pragma unroll
    for (int i = 0; i < 2; i++)
#pragma unroll
        for (int n = 0; n < 8; n++)
#pragma unroll
            for (int t = 0; t < 4; t++) acc[i][n][t] = 0.0f;

#pragma unroll
    for (int p = 0; p < NSTG - 1; p++) {
        uint32_t st = sbase + p * STGB;
#pragma unroll
        for (int i = 0; i < 4; i++) {
            CP16(st + soff[i], aSrc + p * BK + i * rstep);
            CP16(st + STG_A + soff[i], bSrc + p * BK + i * rstep);
        }
        CP_COMMIT();
    }

    uint32_t af[2][8];   // ping-pong A fragments (kk parity)
    uint32_t bf[2][4];   // ping-pong B fragments (j parity)

    for (int kt = 0; kt < KT; kt++) {
        CP_WAIT1();
        __syncthreads();

        int nk = kt + NSTG - 1;
        if (nk < KT) {
            uint32_t st = sbase + (nk % NSTG) * STGB;
#pragma unroll
            for (int i = 0; i < 4; i++) {
                CP16(st + soff[i], aSrc + nk * BK + i * rstep);
                CP16(st + STG_A + soff[i], bSrc + nk * BK + i * rstep);
            }
        }
        CP_COMMIT();

        const uint32_t stA = sbase + (kt % NSTG) * STGB;
        const uint32_t stB = stA + STG_A;

        // prologue: fragments for (kk=0, j=0)
        LDSM_X4(af[0][0], af[0][1], af[0][2], af[0][3], stA + aoff[0]);
        LDSM_X4(af[0][4], af[0][5], af[0][6], af[0][7], stA + aoff[0] + 16 * 128);
        LDSM_X4(bf[0][0], bf[0][1], bf[0][2], bf[0][3], stB + boff[0]);

#pragma unroll
        for (int kk = 0; kk < 4; kk++) {
            const int cp = kk & 1;
#pragma unroll
            for (int j = 0; j < 4; j++) {
                const int jp = j & 1;
                // issue next fragment loads BEFORE consuming current ones
                if (j < 3) {
                    LDSM_X4(bf[jp ^ 1][0], bf[jp ^ 1][1], bf[jp ^ 1][2], bf[jp ^ 1][3],
                            stB + boff[kk] + (j + 1) * 16 * 128);
                } else if (kk < 3) {
                    LDSM_X4(af[cp ^ 1][0], af[cp ^ 1][1], af[cp ^ 1][2], af[cp ^ 1][3],
                            stA + aoff[kk + 1]);
                    LDSM_X4(af[cp ^ 1][4], af[cp ^ 1][5], af[cp ^ 1][6], af[cp ^ 1][7],
                            stA + aoff[kk + 1] + 16 * 128);
                    LDSM_X4(bf[jp ^ 1][0], bf[jp ^ 1][1], bf[jp ^ 1][2], bf[jp ^ 1][3],
                            stB + boff[kk + 1]);
                }
                // 4 MMAs using current fragments
                MMA16816(acc[0][2 * j],     af[cp][0], af[cp][1], af[cp][2], af[cp][3], bf[jp][0], bf[jp][2]);
                MMA16816(acc[0][2 * j + 1], af[cp][0], af[cp][1], af[cp][2], af[cp][3], bf[jp][1], bf[jp][3]);
                MMA16816(acc[1][2 * j],     af[cp][4], af[cp][5], af[cp][6], af[cp][7], bf[jp][0], bf[jp][2]);
                MMA16816(acc[1][2 * j + 1], af[cp][4], af[cp][5], af[cp][6], af[cp][7], bf[jp][1], bf[jp][3]);
            }
        }
    }

    // Epilogue: float2 stores, bias from smem
    const int r0 = wm * 32 + (lane >> 2);
    const int c0 = wn * 64 + (lane & 3) * 2;
    float* ob = out + (size_t)gm0 * NOUT + gn0;
#pragma unroll
    for (int i = 0; i < 2; i++) {
        int row = r0 + i * 16;
#pragma unroll
        for (int n = 0; n < 8; n++) {
            int col = c0 + n * 8;
            float b0 = bsm[col], b1 = bsm[col + 1];
            float2 v0 = make_float2(acc[i][n][0] + b0, acc[i][n][1] + b1);
            float2 v1 = make_float2(acc[i][n][2] + b0, acc[i][n][3] + b1);
            *reinterpret_cast<float2*>(ob + (size_t)row * NOUT + col) = v0;
            *reinterpret_cast<float2*>(ob + (size_t)(row + 8) * NOUT + col) = v1;
        }
    }
}

extern "C" void kernel_launch(void* const* d_in, const int* in_sizes, int n_in,
                              void* d_out, int out_size) {
    const float* x    = (const float*)d_in[0];
    const float* Wqkv = (const float*)d_in[1];
    const float* bqkv = (const float*)d_in[2];
    const float* Aq   = (const float*)d_in[3];
    const float* Bq   = (const float*)d_in[4];
    const float* Ak   = (const float*)d_in[5];
    const float* Bk   = (const float*)d_in[6];
    const float* Av   = (const float*)d_in[7];
    const float* Bv   = (const float*)d_in[8];
    float* out = (float*)d_out;

    int M = in_sizes[0] / DIM;   // 32768
    cudaFuncSetAttribute(gemm_f16, cudaFuncAttributeMaxDynamicSharedMemorySize, SMEM_TOTAL);

    int n8 = M * DIM / 8;
    int nConvBlk = (n8 + 255) / 256;
    int nFoldBlk = (NOUT * DIM + 255) / 256;
    prep_kernel<<<nConvBlk + nFoldBlk, 256>>>(x, n8, nConvBlk, Wqkv, Aq, Bq, Ak, Bk, Av, Bv);

    dim3 grid(NOUT / BN, M / BM);   // 18 x 256
    gemm_f16<<<grid, 256, SMEM_TOTAL>>>(bqkv, out);
}